// round 3
// baseline (speedup 1.0000x reference)
#include <cuda_runtime.h>
#include <math.h>

#define B_  512
#define R_  1152
#define C_  8
#define J_  10
#define O_  16
#define JO_ 160

// Scratch (device globals: no allocations allowed in kernel_launch)
__device__ float g_U[(size_t)B_ * R_ * JO_];   // u_hat [B,R,J*O], fp32, 377 MB
__device__ float g_S[3][B_ * JO_];             // s accumulators per iteration
__device__ float g_V0[B_ * JO_];               // v0
__device__ float g_VSUM[B_ * JO_];             // v0 + v1

// ---------------------------------------------------------------------------
__global__ void k_zero() {
    int i = blockIdx.x * blockDim.x + threadIdx.x;
    if (i < 3 * B_ * JO_) ((float*)g_S)[i] = 0.0f;
}

// ---------------------------------------------------------------------------
// u_hat[b,r,jo] = sum_c W[r,jo,c] * x[b,r,c]; also accumulate sum_r u_hat
// into g_S[0] (iteration 0 has uniform c = 1/J; scaling applied in squash).
// Block: 256 threads = 8 warps = 8 b's sharing one r-chunk & the W smem tile.
// Grid: (B/8, 9) — 9 chunks of 128 r each.
__global__ void __launch_bounds__(256) k_uhat(const float* __restrict__ x,
                                              const float* __restrict__ W) {
    __shared__ float w_s[4][8][164];   // [rr][c][jo], padded 164 to avoid STS conflicts
    const int tid  = threadIdx.x;
    const int warp = tid >> 5, lane = tid & 31;
    const int b    = blockIdx.x * 8 + warp;
    const int r0   = blockIdx.y * 128;

    float sacc[5] = {0.f, 0.f, 0.f, 0.f, 0.f};

    for (int rb = 0; rb < 128; rb += 4) {
        const int rbase = r0 + rb;
        __syncthreads();
        // cooperative load of W[rbase..rbase+4), transposed to [c][jo]
        for (int i = tid; i < 4 * 1280; i += 256) {
            int rr  = i / 1280;
            int rem = i - rr * 1280;           // rem = jo*8 + c
            w_s[rr][rem & 7][rem >> 3] = W[(size_t)(rbase + rr) * 1280 + rem];
        }
        __syncthreads();

        // one coalesced load covers x[b, rbase..rbase+4, 0..8): lane = rr*8+c
        float xv = x[(size_t)b * (R_ * C_) + (size_t)rbase * C_ + lane];

        #pragma unroll
        for (int rr = 0; rr < 4; rr++) {
            float xc[8];
            #pragma unroll
            for (int c = 0; c < 8; c++)
                xc[c] = __shfl_sync(0xffffffffu, xv, rr * 8 + c);

            float* up = &g_U[((size_t)b * R_ + rbase + rr) * JO_];
            #pragma unroll
            for (int k = 0; k < 5; k++) {
                float u = 0.f;
                #pragma unroll
                for (int c = 0; c < 8; c++)
                    u = fmaf(w_s[rr][c][lane + 32 * k], xc[c], u);
                up[lane + 32 * k] = u;
                sacc[k] += u;
            }
        }
    }
    #pragma unroll
    for (int k = 0; k < 5; k++)
        atomicAdd(&g_S[0][b * JO_ + lane + 32 * k], sacc[k]);
}

// ---------------------------------------------------------------------------
// One routing iteration: logits a[b,r,j] = u_hat[b,r,j,:] . V[b,j,:]
// (V = v0 for iter1, v0+v1 for iter2; b_ij never materialized), softmax over
// j=10, accumulate s[b,j,o] = sum_r c * u_hat.
// One warp owns (b, slice of 128 r). Lane l holds jo = l + 32k, k=0..4:
// lanes 0-15 hold even j (= 2k), lanes 16-31 odd j (= 2k+1).
__global__ void __launch_bounds__(256) k_route(int vsel, int ssel) {
    const int lane = threadIdx.x & 31;
    const int unit = blockIdx.x * 8 + (threadIdx.x >> 5);
    const int b    = unit / 9;
    const int sl   = unit - b * 9;

    const float* __restrict__ V = vsel ? g_VSUM : g_V0;

    float v[5], sacc[5] = {0.f, 0.f, 0.f, 0.f, 0.f};
    #pragma unroll
    for (int k = 0; k < 5; k++)
        v[k] = V[b * JO_ + lane + 32 * k];

    const float* __restrict__ up =
        &g_U[((size_t)b * R_ + (size_t)sl * 128) * JO_ + lane];

    #pragma unroll 2
    for (int r = 0; r < 128; r++) {
        float u[5], ap[5];
        #pragma unroll
        for (int k = 0; k < 5; k++) u[k] = up[32 * k];
        up += JO_;

        #pragma unroll
        for (int k = 0; k < 5; k++) ap[k] = u[k] * v[k];

        // reduce over o (16 lanes per j-group)
        #pragma unroll
        for (int d = 1; d < 16; d <<= 1) {
            #pragma unroll
            for (int k = 0; k < 5; k++)
                ap[k] += __shfl_xor_sync(0xffffffffu, ap[k], d);
        }
        // ap[k] = a[j], j = 2k + (lane>>4). Softmax over all 10 j:
        float m = ap[0];
        #pragma unroll
        for (int k = 1; k < 5; k++) m = fmaxf(m, ap[k]);
        m = fmaxf(m, __shfl_xor_sync(0xffffffffu, m, 16));

        float e[5], z = 0.f;
        #pragma unroll
        for (int k = 0; k < 5; k++) { e[k] = __expf(ap[k] - m); z += e[k]; }
        z += __shfl_xor_sync(0xffffffffu, z, 16);
        float rz = __fdividef(1.0f, z);

        #pragma unroll
        for (int k = 0; k < 5; k++)
            sacc[k] = fmaf(e[k] * rz, u[k], sacc[k]);
    }

    float* __restrict__ Sout = g_S[ssel];
    #pragma unroll
    for (int k = 0; k < 5; k++)
        atomicAdd(&Sout[b * JO_ + lane + 32 * k], sacc[k]);
}

// ---------------------------------------------------------------------------
// v = squash(S * scale). mode 0: write g_V0. mode 1: g_VSUM = v + g_V0.
// mode 2: write dout (final output, [B,J,O,1] contiguous).
__global__ void k_squash(int ssel, float scale, int mode,
                         float* __restrict__ dout) {
    int i = blockIdx.x * blockDim.x + threadIdx.x;   // over B*J = 5120
    if (i >= B_ * J_) return;
    const float* s = g_S[ssel] + (size_t)i * O_;

    float sv[O_];
    float sq = 0.f;
    #pragma unroll
    for (int o = 0; o < O_; o++) {
        float t = s[o] * scale;
        sv[o] = t;
        sq += t * t;
    }
    float f = (sq / (1.0f + sq)) * rsqrtf(sq + 1e-8f);

    #pragma unroll
    for (int o = 0; o < O_; o++) {
        float vv = sv[o] * f;
        if (mode == 0)      g_V0[(size_t)i * O_ + o]   = vv;
        else if (mode == 1) g_VSUM[(size_t)i * O_ + o] = vv + g_V0[(size_t)i * O_ + o];
        else                dout[(size_t)i * O_ + o]   = vv;
    }
}

// ---------------------------------------------------------------------------
extern "C" void kernel_launch(void* const* d_in, const int* in_sizes, int n_in,
                              void* d_out, int out_size) {
    const float* x = (const float*)d_in[0];   // [512,1152,8]
    const float* W = (const float*)d_in[1];   // [1152,10,16,8]
    float* out = (float*)d_out;               // [512,10,16,1]
    (void)in_sizes; (void)n_in; (void)out_size;

    k_zero<<<240, 1024>>>();                          // zero S0,S1,S2
    k_uhat<<<dim3(64, 9), 256>>>(x, W);               // u_hat + sum_r -> S0
    k_squash<<<20, 256>>>(0, 1.0f / (float)J_, 0, nullptr);  // v0
    k_route<<<576, 256>>>(0, 1);                      // iter 1 -> S1 (logits u.v0)
    k_squash<<<20, 256>>>(1, 1.0f, 1, nullptr);       // v1, VSUM = v0+v1
    k_route<<<576, 256>>>(1, 2);                      // iter 2 -> S2 (logits u.(v0+v1))
    k_squash<<<20, 256>>>(2, 1.0f, 2, out);           // v2 -> output
}

// round 4
// speedup vs baseline: 1.0181x; 1.0181x over previous
#include <cuda_runtime.h>
#include <math.h>

#define B_  512
#define R_  1152
#define C_  8
#define J_  10
#define O_  16
#define JO_ 160

// Scratch (device globals: no allocations allowed in kernel_launch)
__device__ float g_U[(size_t)B_ * R_ * JO_];   // u_hat [B,R,J*O], fp32, 377 MB
__device__ float g_S[3][B_ * JO_];             // s accumulators per iteration
__device__ float g_V0[B_ * JO_];               // v0
__device__ float g_VSUM[B_ * JO_];             // v0 + v1

// ---------------------------------------------------------------------------
__global__ void k_zero() {
    int i = blockIdx.x * blockDim.x + threadIdx.x;
    if (i < 3 * B_ * JO_) ((float*)g_S)[i] = 0.0f;
}

// ---------------------------------------------------------------------------
// u_hat[b,r,jo] = sum_c W[r,jo,c] * x[b,r,c]; also accumulate sum_r u_hat
// into g_S[0] (iteration 0 has uniform c = 1/J; scaling applied in squash).
// Block: 256 threads = 8 warps = 8 b's sharing one r-chunk & the W smem tile.
// Grid: (B/8, 9) — 9 chunks of 128 r each.
__global__ void __launch_bounds__(256) k_uhat(const float* __restrict__ x,
                                              const float* __restrict__ W) {
    __shared__ float w_s[4][8][164];   // [rr][c][jo], padded 164 to avoid STS conflicts
    const int tid  = threadIdx.x;
    const int warp = tid >> 5, lane = tid & 31;
    const int b    = blockIdx.x * 8 + warp;
    const int r0   = blockIdx.y * 128;

    float sacc[5] = {0.f, 0.f, 0.f, 0.f, 0.f};

    for (int rb = 0; rb < 128; rb += 4) {
        const int rbase = r0 + rb;
        __syncthreads();
        // cooperative load of W[rbase..rbase+4), transposed to [c][jo]
        for (int i = tid; i < 4 * 1280; i += 256) {
            int rr  = i / 1280;
            int rem = i - rr * 1280;           // rem = jo*8 + c
            w_s[rr][rem & 7][rem >> 3] = W[(size_t)(rbase + rr) * 1280 + rem];
        }
        __syncthreads();

        // one coalesced load covers x[b, rbase..rbase+4, 0..8): lane = rr*8+c
        float xv = x[(size_t)b * (R_ * C_) + (size_t)rbase * C_ + lane];

        #pragma unroll
        for (int rr = 0; rr < 4; rr++) {
            float xc[8];
            #pragma unroll
            for (int c = 0; c < 8; c++)
                xc[c] = __shfl_sync(0xffffffffu, xv, rr * 8 + c);

            float* up = &g_U[((size_t)b * R_ + rbase + rr) * JO_];
            #pragma unroll
            for (int k = 0; k < 5; k++) {
                float u = 0.f;
                #pragma unroll
                for (int c = 0; c < 8; c++)
                    u = fmaf(w_s[rr][c][lane + 32 * k], xc[c], u);
                up[lane + 32 * k] = u;
                sacc[k] += u;
            }
        }
    }
    #pragma unroll
    for (int k = 0; k < 5; k++)
        atomicAdd(&g_S[0][b * JO_ + lane + 32 * k], sacc[k]);
}

// ---------------------------------------------------------------------------
// One routing iteration: logits a[b,r,j] = u_hat[b,r,j,:] . V[b,j,:]
// (V = v0 for iter1, v0+v1 for iter2; b_ij never materialized), softmax over
// j=10, accumulate s[b,j,o] = sum_r c * u_hat.
// One warp owns (b, slice of 128 r). Lane l holds jo = l + 32k, k=0..4:
// lanes 0-15 hold even j (= 2k), lanes 16-31 odd j (= 2k+1).
__global__ void __launch_bounds__(256) k_route(int vsel, int ssel) {
    const int lane = threadIdx.x & 31;
    const int unit = blockIdx.x * 8 + (threadIdx.x >> 5);
    const int b    = unit / 9;
    const int sl   = unit - b * 9;

    const float* __restrict__ V = vsel ? g_VSUM : g_V0;

    float v[5], sacc[5] = {0.f, 0.f, 0.f, 0.f, 0.f};
    #pragma unroll
    for (int k = 0; k < 5; k++)
        v[k] = V[b * JO_ + lane + 32 * k];

    const float* __restrict__ up =
        &g_U[((size_t)b * R_ + (size_t)sl * 128) * JO_ + lane];

    #pragma unroll 2
    for (int r = 0; r < 128; r++) {
        float u[5], ap[5];
        #pragma unroll
        for (int k = 0; k < 5; k++) u[k] = up[32 * k];
        up += JO_;

        #pragma unroll
        for (int k = 0; k < 5; k++) ap[k] = u[k] * v[k];

        // reduce over o (16 lanes per j-group)
        #pragma unroll
        for (int d = 1; d < 16; d <<= 1) {
            #pragma unroll
            for (int k = 0; k < 5; k++)
                ap[k] += __shfl_xor_sync(0xffffffffu, ap[k], d);
        }
        // ap[k] = a[j], j = 2k + (lane>>4). Softmax over all 10 j:
        float m = ap[0];
        #pragma unroll
        for (int k = 1; k < 5; k++) m = fmaxf(m, ap[k]);
        m = fmaxf(m, __shfl_xor_sync(0xffffffffu, m, 16));

        float e[5], z = 0.f;
        #pragma unroll
        for (int k = 0; k < 5; k++) { e[k] = __expf(ap[k] - m); z += e[k]; }
        z += __shfl_xor_sync(0xffffffffu, z, 16);
        float rz = __fdividef(1.0f, z);

        #pragma unroll
        for (int k = 0; k < 5; k++)
            sacc[k] = fmaf(e[k] * rz, u[k], sacc[k]);
    }

    float* __restrict__ Sout = g_S[ssel];
    #pragma unroll
    for (int k = 0; k < 5; k++)
        atomicAdd(&Sout[b * JO_ + lane + 32 * k], sacc[k]);
}

// ---------------------------------------------------------------------------
// v = squash(S * scale). mode 0: write g_V0. mode 1: g_VSUM = v + g_V0.
// mode 2: write dout (final output, [B,J,O,1] contiguous).
__global__ void k_squash(int ssel, float scale, int mode,
                         float* __restrict__ dout) {
    int i = blockIdx.x * blockDim.x + threadIdx.x;   // over B*J = 5120
    if (i >= B_ * J_) return;
    const float* s = g_S[ssel] + (size_t)i * O_;

    float sv[O_];
    float sq = 0.f;
    #pragma unroll
    for (int o = 0; o < O_; o++) {
        float t = s[o] * scale;
        sv[o] = t;
        sq += t * t;
    }
    float f = (sq / (1.0f + sq)) * rsqrtf(sq + 1e-8f);

    #pragma unroll
    for (int o = 0; o < O_; o++) {
        float vv = sv[o] * f;
        if (mode == 0)      g_V0[(size_t)i * O_ + o]   = vv;
        else if (mode == 1) g_VSUM[(size_t)i * O_ + o] = vv + g_V0[(size_t)i * O_ + o];
        else                dout[(size_t)i * O_ + o]   = vv;
    }
}

// ---------------------------------------------------------------------------
extern "C" void kernel_launch(void* const* d_in, const int* in_sizes, int n_in,
                              void* d_out, int out_size) {
    const float* x = (const float*)d_in[0];   // [512,1152,8]
    const float* W = (const float*)d_in[1];   // [1152,10,16,8]
    float* out = (float*)d_out;               // [512,10,16,1]
    (void)in_sizes; (void)n_in; (void)out_size;

    k_zero<<<240, 1024>>>();                          // zero S0,S1,S2
    k_uhat<<<dim3(64, 9), 256>>>(x, W);               // u_hat + sum_r -> S0
    k_squash<<<20, 256>>>(0, 1.0f / (float)J_, 0, nullptr);  // v0
    k_route<<<576, 256>>>(0, 1);                      // iter 1 -> S1 (logits u.v0)
    k_squash<<<20, 256>>>(1, 1.0f, 1, nullptr);       // v1, VSUM = v0+v1
    k_route<<<576, 256>>>(1, 2);                      // iter 2 -> S2 (logits u.(v0+v1))
    k_squash<<<20, 256>>>(2, 1.0f, 2, out);           // v2 -> output
}